// round 12
// baseline (speedup 1.0000x reference)
#include <cuda_runtime.h>

#define TSEQ 512
#define BB 16
#define NTHREADS 384
#define BATCH 2048
#define NBLOCKS (BATCH / BB)   // 128

// smem layout (float indices). Weight matrices gate-adjacent split (as R11):
//   WA[(k2*64+m)*4 + g*2 + p] = w[(g*64+m)*64 + 2*k2+p], g in {0,1}; WB likewise g in {2,3}
#define OFF_W0A   0
#define OFF_W0B   8192
#define OFF_WI1A  16384
#define OFF_WI1B  24576
#define OFF_WH1A  32768
#define OFF_WH1B  40960
#define OFF_H0BUF 49152      // [2][16][64] double-buffered h0
#define OFF_H1    51200      // [16][64]
#define OFF_XB    52224      // [2][16]
#define SMEM_FLOATS (OFF_XB + 32)
#define SMEM_BYTES  (SMEM_FLOATS * 4)   // 209024

typedef unsigned long long ull;

__device__ __forceinline__ void unpack2(ull v, float& lo, float& hi){
    asm("mov.b64 {%0,%1}, %2;" : "=f"(lo), "=f"(hi) : "l"(v));
}
__device__ __forceinline__ ull ffma2(ull a, ull b, ull c){
    ull d; asm("fma.rn.f32x2 %0, %1, %2, %3;" : "=l"(d) : "l"(a), "l"(b), "l"(c)); return d;
}
__device__ __forceinline__ float fast_ex2(float x){ float y; asm("ex2.approx.f32 %0, %1;" : "=f"(y) : "f"(x)); return y; }
__device__ __forceinline__ float fast_rcp(float x){ float y; asm("rcp.approx.f32 %0, %1;" : "=f"(y) : "f"(x)); return y; }

__device__ __forceinline__ float sigm_(float v){
    float e = fast_ex2(-1.4426950408889634f * v);
    return fast_rcp(1.0f + e);
}
__device__ __forceinline__ float tanh_(float v){
    float e = fast_ex2(-2.8853900817779268f * v);
    return fmaf(2.0f, fast_rcp(1.0f + e), -1.0f);
}

// acc[g][bb] += sum_k h[bb][k] * W[k][g*64+m], 4 bb rows (layer-1 threads)
__device__ __forceinline__ void gemm4(ull acc[4][4],
                                      const float* __restrict__ Wa,
                                      const float* __restrict__ Wb,
                                      const float* __restrict__ hrow, int m4)
{
    const float* wa = Wa + m4;
    const float* wb = Wb + m4;
    #pragma unroll
    for (int k4 = 0; k4 < 16; ++k4) {
        ulonglong2 hv[4];
        #pragma unroll
        for (int bb = 0; bb < 4; ++bb)
            hv[bb] = *(const ulonglong2*)(hrow + bb * 64 + 4 * k4);
        ulonglong2 wA1 = *(const ulonglong2*)(wa + 512 * k4);
        ulonglong2 wB1 = *(const ulonglong2*)(wb + 512 * k4);
        ulonglong2 wA2 = *(const ulonglong2*)(wa + 512 * k4 + 256);
        ulonglong2 wB2 = *(const ulonglong2*)(wb + 512 * k4 + 256);
        #pragma unroll
        for (int bb = 0; bb < 4; ++bb) {
            acc[0][bb] = ffma2(hv[bb].x, wA1.x, acc[0][bb]);
            acc[1][bb] = ffma2(hv[bb].x, wA1.y, acc[1][bb]);
            acc[2][bb] = ffma2(hv[bb].x, wB1.x, acc[2][bb]);
            acc[3][bb] = ffma2(hv[bb].x, wB1.y, acc[3][bb]);
            acc[0][bb] = ffma2(hv[bb].y, wA2.x, acc[0][bb]);
            acc[1][bb] = ffma2(hv[bb].y, wA2.y, acc[1][bb]);
            acc[2][bb] = ffma2(hv[bb].y, wB2.x, acc[2][bb]);
            acc[3][bb] = ffma2(hv[bb].y, wB2.y, acc[3][bb]);
        }
    }
}

// 8-bb variant (layer-0 threads)
__device__ __forceinline__ void gemm8(ull acc[4][8],
                                      const float* __restrict__ Wa,
                                      const float* __restrict__ Wb,
                                      const float* __restrict__ hrow, int m4)
{
    const float* wa = Wa + m4;
    const float* wb = Wb + m4;
    #pragma unroll
    for (int k4 = 0; k4 < 16; ++k4) {
        ulonglong2 hv[8];
        #pragma unroll
        for (int bb = 0; bb < 8; ++bb)
            hv[bb] = *(const ulonglong2*)(hrow + bb * 64 + 4 * k4);
        ulonglong2 wA1 = *(const ulonglong2*)(wa + 512 * k4);
        ulonglong2 wB1 = *(const ulonglong2*)(wb + 512 * k4);
        ulonglong2 wA2 = *(const ulonglong2*)(wa + 512 * k4 + 256);
        ulonglong2 wB2 = *(const ulonglong2*)(wb + 512 * k4 + 256);
        #pragma unroll
        for (int bb = 0; bb < 8; ++bb) {
            acc[0][bb] = ffma2(hv[bb].x, wA1.x, acc[0][bb]);
            acc[1][bb] = ffma2(hv[bb].x, wA1.y, acc[1][bb]);
            acc[2][bb] = ffma2(hv[bb].x, wB1.x, acc[2][bb]);
            acc[3][bb] = ffma2(hv[bb].x, wB1.y, acc[3][bb]);
            acc[0][bb] = ffma2(hv[bb].y, wA2.x, acc[0][bb]);
            acc[1][bb] = ffma2(hv[bb].y, wA2.y, acc[1][bb]);
            acc[2][bb] = ffma2(hv[bb].y, wB2.x, acc[2][bb]);
            acc[3][bb] = ffma2(hv[bb].y, wB2.y, acc[3][bb]);
        }
    }
}

__global__ __launch_bounds__(NTHREADS)
void lstm2_fused_kernel(const float* __restrict__ x,
                        const float* __restrict__ w_ih0, const float* __restrict__ w_hh0,
                        const float* __restrict__ b_ih0, const float* __restrict__ b_hh0,
                        const float* __restrict__ w_ih1, const float* __restrict__ w_hh1,
                        const float* __restrict__ b_ih1, const float* __restrict__ b_hh1,
                        const float* __restrict__ w_fc,  const float* __restrict__ b_fc,
                        float* __restrict__ out)
{
    extern __shared__ float smem[];
    float* W0A   = smem + OFF_W0A;
    float* W0B   = smem + OFF_W0B;
    float* WI1A  = smem + OFF_WI1A;
    float* WI1B  = smem + OFF_WI1B;
    float* WH1A  = smem + OFF_WH1A;
    float* WH1B  = smem + OFF_WH1B;
    float* h0buf = smem + OFF_H0BUF;   // [2][1024]
    float* h1s   = smem + OFF_H1;
    float* xbuf  = smem + OFF_XB;      // [2][16]

    const int tid   = threadIdx.x;
    const int bbase = blockIdx.x * BB;

    // ---- weights -> smem (gate-adjacent split layout, as R11) ----
    for (int idx = tid; idx < 8192; idx += NTHREADS) {
        int k2 = idx >> 8;
        int m  = (idx >> 2) & 63;
        int g  = idx & 3;
        int srcoff = (g * 64 + m) * 64 + 2 * k2;
        int dsthalf = (g >> 1);
        int dstoff = (k2 * 64 + m) * 4 + (g & 1) * 2;
        float2 v0 = *(const float2*)(w_hh0 + srcoff);
        float2 v1 = *(const float2*)(w_ih1 + srcoff);
        float2 v2 = *(const float2*)(w_hh1 + srcoff);
        *(float2*)((dsthalf ? W0B  : W0A)  + dstoff) = v0;
        *(float2*)((dsthalf ? WI1B : WI1A) + dstoff) = v1;
        *(float2*)((dsthalf ? WH1B : WH1A) + dstoff) = v2;
    }
    for (int idx = tid; idx < 2 * 1024; idx += NTHREADS) h0buf[idx] = 0.0f;
    for (int idx = tid; idx < 1024; idx += NTHREADS) h1s[idx] = 0.0f;
    if (tid < BB) xbuf[tid] = x[(bbase + tid) * TSEQ + 0];   // xbuf[0][*] = x(t=0)

    const bool isA = (tid < 128);     // layer-0 group: warps 0-3
    const int  btid = tid - 128;      // layer-1 group lane id

    // group A mapping: unit m, 8 batch rows (bg*8..+7)
    const int mA  = tid & 63;
    const int bgA = tid >> 6;         // 0 or 1
    // group B mapping: unit m, 4 batch rows (bg4*4..+3)
    const int mB  = btid & 63;
    const int bg4 = btid >> 6;        // 0..3

    float bias0[4], wi0[4], bias1[4];
    if (isA) {
        #pragma unroll
        for (int g = 0; g < 4; ++g) {
            int j = g * 64 + mA;
            bias0[g] = b_ih0[j] + b_hh0[j];
            wi0[g]   = w_ih0[j];
        }
    } else {
        #pragma unroll
        for (int g = 0; g < 4; ++g) {
            int j = g * 64 + mB;
            bias1[g] = b_ih1[j] + b_hh1[j];
        }
    }

    float c0[8] = {0,0,0,0,0,0,0,0};  // A state (8 bb)
    float c1[4] = {0,0,0,0};          // B state (4 bb)

    __syncthreads();

    // phases: p in [0, 512]; A does l0(t=p) for p<512; B does l1(t=p-1) for p>=1
    for (int p = 0; p <= TSEQ; ++p) {
        const int rd = (p + 1) & 1;   // both groups read h0(t=p-1) here
        const int wr = p & 1;         // A writes h0(t=p) here

        if (isA) {
            if (p < TSEQ) {
                const float* hr = h0buf + rd * 1024 + bgA * 512;
                ull acc[4][8];
                #pragma unroll
                for (int g = 0; g < 4; ++g)
                    #pragma unroll
                    for (int bb = 0; bb < 8; ++bb) acc[g][bb] = 0ULL;
                gemm8(acc, W0A, W0B, hr, mA * 4);

                float* hw = h0buf + wr * 1024 + bgA * 512 + mA;
                const float* xr = xbuf + wr * 16 + bgA * 8;   // xbuf[p&1] = x(t=p)
                #pragma unroll
                for (int bb = 0; bb < 8; ++bb) {
                    float xv = xr[bb];
                    float s[4];
                    #pragma unroll
                    for (int g = 0; g < 4; ++g) {
                        float lo, hi;
                        unpack2(acc[g][bb], lo, hi);
                        s[g] = fmaf(xv, wi0[g], bias0[g]) + (lo + hi);
                    }
                    float iv = sigm_(s[0]);
                    float fv = sigm_(s[1]);
                    float gv = tanh_(s[2]);
                    float ov = sigm_(s[3]);
                    c0[bb] = fmaf(fv, c0[bb], iv * gv);
                    hw[bb * 64] = ov * tanh_(c0[bb]);
                }
                // prefetch x(t=p+1) into xbuf[(p+1)&1]
                if (tid < BB && p + 1 < TSEQ)
                    xbuf[rd * 16 + tid] = x[(bbase + tid) * TSEQ + (p + 1)];
            }
        } else {
            if (p >= 1) {
                const float* hr0 = h0buf + rd * 1024 + bg4 * 256;
                const float* hr1 = h1s + bg4 * 256;
                ull acc[4][4];
                #pragma unroll
                for (int g = 0; g < 4; ++g)
                    #pragma unroll
                    for (int bb = 0; bb < 4; ++bb) acc[g][bb] = 0ULL;
                gemm4(acc, WI1A, WI1B, hr0, mB * 4);
                gemm4(acc, WH1A, WH1B, hr1, mB * 4);

                float* hw = h1s + bg4 * 256 + mB;
                #pragma unroll
                for (int bb = 0; bb < 4; ++bb) {
                    float s[4];
                    #pragma unroll
                    for (int g = 0; g < 4; ++g) {
                        float lo, hi;
                        unpack2(acc[g][bb], lo, hi);
                        s[g] = bias1[g] + (lo + hi);
                    }
                    float iv = sigm_(s[0]);
                    float fv = sigm_(s[1]);
                    float gv = tanh_(s[2]);
                    float ov = sigm_(s[3]);
                    c1[bb] = fmaf(fv, c1[bb], iv * gv);
                    hw[bb * 64] = ov * tanh_(c1[bb]);
                }
            }
        }
        __syncthreads();
    }

    // ---- final FC ----
    if (tid < BB * 3) {
        int bb  = tid / 3;
        int cls = tid - bb * 3;
        float s = b_fc[cls];
        #pragma unroll 8
        for (int mm = 0; mm < 64; ++mm)
            s = fmaf(h1s[bb * 64 + mm], w_fc[cls * 64 + mm], s);
        out[(bbase + bb) * 3 + cls] = s;
    }
}

extern "C" void kernel_launch(void* const* d_in, const int* in_sizes, int n_in,
                              void* d_out, int out_size)
{
    const float* x     = (const float*)d_in[0];
    const float* w_ih0 = (const float*)d_in[1];
    const float* w_hh0 = (const float*)d_in[2];
    const float* b_ih0 = (const float*)d_in[3];
    const float* b_hh0 = (const float*)d_in[4];
    const float* w_ih1 = (const float*)d_in[5];
    const float* w_hh1 = (const float*)d_in[6];
    const float* b_ih1 = (const float*)d_in[7];
    const float* b_hh1 = (const float*)d_in[8];
    const float* w_fc  = (const float*)d_in[9];
    const float* b_fc  = (const float*)d_in[10];
    float* out = (float*)d_out;

    cudaFuncSetAttribute(lstm2_fused_kernel,
                         cudaFuncAttributeMaxDynamicSharedMemorySize, SMEM_BYTES);

    lstm2_fused_kernel<<<NBLOCKS, NTHREADS, SMEM_BYTES>>>(
        x, w_ih0, w_hh0, b_ih0, b_hh0,
        w_ih1, w_hh1, b_ih1, b_hh1,
        w_fc, b_fc, out);
}

// round 13
// speedup vs baseline: 1.0005x; 1.0005x over previous
#include <cuda_runtime.h>

#define TSEQ 512
#define BB 16
#define NTHREADS 384
#define BATCH 2048
#define NBLOCKS (BATCH / BB)   // 128

// smem layout (float indices). Weight matrices gate-adjacent split (as R11):
//   WA[(k2*64+m)*4 + g*2 + p] = w[(g*64+m)*64 + 2*k2+p], g in {0,1}; WB likewise g in {2,3}
#define OFF_W0A   0
#define OFF_W0B   8192
#define OFF_WI1A  16384
#define OFF_WI1B  24576
#define OFF_WH1A  32768
#define OFF_WH1B  40960
#define OFF_H0BUF 49152      // [2][16][64] double-buffered h0
#define OFF_H1    51200      // [16][64]
#define OFF_XB    52224      // [2][16]
#define SMEM_FLOATS (OFF_XB + 32)
#define SMEM_BYTES  (SMEM_FLOATS * 4)   // 209024

typedef unsigned long long ull;

__device__ __forceinline__ void unpack2(ull v, float& lo, float& hi){
    asm("mov.b64 {%0,%1}, %2;" : "=f"(lo), "=f"(hi) : "l"(v));
}
__device__ __forceinline__ ull ffma2(ull a, ull b, ull c){
    ull d; asm("fma.rn.f32x2 %0, %1, %2, %3;" : "=l"(d) : "l"(a), "l"(b), "l"(c)); return d;
}
__device__ __forceinline__ float fast_ex2(float x){ float y; asm("ex2.approx.f32 %0, %1;" : "=f"(y) : "f"(x)); return y; }
__device__ __forceinline__ float fast_rcp(float x){ float y; asm("rcp.approx.f32 %0, %1;" : "=f"(y) : "f"(x)); return y; }

__device__ __forceinline__ float sigm_(float v){
    float e = fast_ex2(-1.4426950408889634f * v);
    return fast_rcp(1.0f + e);
}
__device__ __forceinline__ float tanh_(float v){
    float e = fast_ex2(-2.8853900817779268f * v);
    return fmaf(2.0f, fast_rcp(1.0f + e), -1.0f);
}

// acc[g][bb] += sum_k h[bb][k] * W[k][g*64+m], 4 bb rows (layer-1 threads)
__device__ __forceinline__ void gemm4(ull acc[4][4],
                                      const float* __restrict__ Wa,
                                      const float* __restrict__ Wb,
                                      const float* __restrict__ hrow, int m4)
{
    const float* wa = Wa + m4;
    const float* wb = Wb + m4;
    #pragma unroll
    for (int k4 = 0; k4 < 16; ++k4) {
        ulonglong2 hv[4];
        #pragma unroll
        for (int bb = 0; bb < 4; ++bb)
            hv[bb] = *(const ulonglong2*)(hrow + bb * 64 + 4 * k4);
        ulonglong2 wA1 = *(const ulonglong2*)(wa + 512 * k4);
        ulonglong2 wB1 = *(const ulonglong2*)(wb + 512 * k4);
        ulonglong2 wA2 = *(const ulonglong2*)(wa + 512 * k4 + 256);
        ulonglong2 wB2 = *(const ulonglong2*)(wb + 512 * k4 + 256);
        #pragma unroll
        for (int bb = 0; bb < 4; ++bb) {
            acc[0][bb] = ffma2(hv[bb].x, wA1.x, acc[0][bb]);
            acc[1][bb] = ffma2(hv[bb].x, wA1.y, acc[1][bb]);
            acc[2][bb] = ffma2(hv[bb].x, wB1.x, acc[2][bb]);
            acc[3][bb] = ffma2(hv[bb].x, wB1.y, acc[3][bb]);
            acc[0][bb] = ffma2(hv[bb].y, wA2.x, acc[0][bb]);
            acc[1][bb] = ffma2(hv[bb].y, wA2.y, acc[1][bb]);
            acc[2][bb] = ffma2(hv[bb].y, wB2.x, acc[2][bb]);
            acc[3][bb] = ffma2(hv[bb].y, wB2.y, acc[3][bb]);
        }
    }
}

// 8-bb variant (layer-0 threads)
__device__ __forceinline__ void gemm8(ull acc[4][8],
                                      const float* __restrict__ Wa,
                                      const float* __restrict__ Wb,
                                      const float* __restrict__ hrow, int m4)
{
    const float* wa = Wa + m4;
    const float* wb = Wb + m4;
    #pragma unroll
    for (int k4 = 0; k4 < 16; ++k4) {
        ulonglong2 hv[8];
        #pragma unroll
        for (int bb = 0; bb < 8; ++bb)
            hv[bb] = *(const ulonglong2*)(hrow + bb * 64 + 4 * k4);
        ulonglong2 wA1 = *(const ulonglong2*)(wa + 512 * k4);
        ulonglong2 wB1 = *(const ulonglong2*)(wb + 512 * k4);
        ulonglong2 wA2 = *(const ulonglong2*)(wa + 512 * k4 + 256);
        ulonglong2 wB2 = *(const ulonglong2*)(wb + 512 * k4 + 256);
        #pragma unroll
        for (int bb = 0; bb < 8; ++bb) {
            acc[0][bb] = ffma2(hv[bb].x, wA1.x, acc[0][bb]);
            acc[1][bb] = ffma2(hv[bb].x, wA1.y, acc[1][bb]);
            acc[2][bb] = ffma2(hv[bb].x, wB1.x, acc[2][bb]);
            acc[3][bb] = ffma2(hv[bb].x, wB1.y, acc[3][bb]);
            acc[0][bb] = ffma2(hv[bb].y, wA2.x, acc[0][bb]);
            acc[1][bb] = ffma2(hv[bb].y, wA2.y, acc[1][bb]);
            acc[2][bb] = ffma2(hv[bb].y, wB2.x, acc[2][bb]);
            acc[3][bb] = ffma2(hv[bb].y, wB2.y, acc[3][bb]);
        }
    }
}

__global__ __launch_bounds__(NTHREADS)
void lstm2_fused_kernel(const float* __restrict__ x,
                        const float* __restrict__ w_ih0, const float* __restrict__ w_hh0,
                        const float* __restrict__ b_ih0, const float* __restrict__ b_hh0,
                        const float* __restrict__ w_ih1, const float* __restrict__ w_hh1,
                        const float* __restrict__ b_ih1, const float* __restrict__ b_hh1,
                        const float* __restrict__ w_fc,  const float* __restrict__ b_fc,
                        float* __restrict__ out)
{
    extern __shared__ float smem[];
    float* W0A   = smem + OFF_W0A;
    float* W0B   = smem + OFF_W0B;
    float* WI1A  = smem + OFF_WI1A;
    float* WI1B  = smem + OFF_WI1B;
    float* WH1A  = smem + OFF_WH1A;
    float* WH1B  = smem + OFF_WH1B;
    float* h0buf = smem + OFF_H0BUF;   // [2][1024]
    float* h1s   = smem + OFF_H1;
    float* xbuf  = smem + OFF_XB;      // [2][16]

    const int tid   = threadIdx.x;
    const int bbase = blockIdx.x * BB;

    // ---- weights -> smem (gate-adjacent split layout, as R11) ----
    for (int idx = tid; idx < 8192; idx += NTHREADS) {
        int k2 = idx >> 8;
        int m  = (idx >> 2) & 63;
        int g  = idx & 3;
        int srcoff = (g * 64 + m) * 64 + 2 * k2;
        int dsthalf = (g >> 1);
        int dstoff = (k2 * 64 + m) * 4 + (g & 1) * 2;
        float2 v0 = *(const float2*)(w_hh0 + srcoff);
        float2 v1 = *(const float2*)(w_ih1 + srcoff);
        float2 v2 = *(const float2*)(w_hh1 + srcoff);
        *(float2*)((dsthalf ? W0B  : W0A)  + dstoff) = v0;
        *(float2*)((dsthalf ? WI1B : WI1A) + dstoff) = v1;
        *(float2*)((dsthalf ? WH1B : WH1A) + dstoff) = v2;
    }
    for (int idx = tid; idx < 2 * 1024; idx += NTHREADS) h0buf[idx] = 0.0f;
    for (int idx = tid; idx < 1024; idx += NTHREADS) h1s[idx] = 0.0f;
    if (tid < BB) xbuf[tid] = x[(bbase + tid) * TSEQ + 0];   // xbuf[0][*] = x(t=0)

    const bool isA = (tid < 128);     // layer-0 group: warps 0-3
    const int  btid = tid - 128;      // layer-1 group lane id

    // group A mapping: unit m, 8 batch rows (bg*8..+7)
    const int mA  = tid & 63;
    const int bgA = tid >> 6;         // 0 or 1
    // group B mapping: unit m, 4 batch rows (bg4*4..+3)
    const int mB  = btid & 63;
    const int bg4 = btid >> 6;        // 0..3

    float bias0[4], wi0[4], bias1[4];
    if (isA) {
        #pragma unroll
        for (int g = 0; g < 4; ++g) {
            int j = g * 64 + mA;
            bias0[g] = b_ih0[j] + b_hh0[j];
            wi0[g]   = w_ih0[j];
        }
    } else {
        #pragma unroll
        for (int g = 0; g < 4; ++g) {
            int j = g * 64 + mB;
            bias1[g] = b_ih1[j] + b_hh1[j];
        }
    }

    float c0[8] = {0,0,0,0,0,0,0,0};  // A state (8 bb)
    float c1[4] = {0,0,0,0};          // B state (4 bb)

    __syncthreads();

    // phases: p in [0, 512]; A does l0(t=p) for p<512; B does l1(t=p-1) for p>=1
    for (int p = 0; p <= TSEQ; ++p) {
        const int rd = (p + 1) & 1;   // both groups read h0(t=p-1) here
        const int wr = p & 1;         // A writes h0(t=p) here

        if (isA) {
            if (p < TSEQ) {
                const float* hr = h0buf + rd * 1024 + bgA * 512;
                ull acc[4][8];
                #pragma unroll
                for (int g = 0; g < 4; ++g)
                    #pragma unroll
                    for (int bb = 0; bb < 8; ++bb) acc[g][bb] = 0ULL;
                gemm8(acc, W0A, W0B, hr, mA * 4);

                float* hw = h0buf + wr * 1024 + bgA * 512 + mA;
                const float* xr = xbuf + wr * 16 + bgA * 8;   // xbuf[p&1] = x(t=p)
                #pragma unroll
                for (int bb = 0; bb < 8; ++bb) {
                    float xv = xr[bb];
                    float s[4];
                    #pragma unroll
                    for (int g = 0; g < 4; ++g) {
                        float lo, hi;
                        unpack2(acc[g][bb], lo, hi);
                        s[g] = fmaf(xv, wi0[g], bias0[g]) + (lo + hi);
                    }
                    float iv = sigm_(s[0]);
                    float fv = sigm_(s[1]);
                    float gv = tanh_(s[2]);
                    float ov = sigm_(s[3]);
                    c0[bb] = fmaf(fv, c0[bb], iv * gv);
                    hw[bb * 64] = ov * tanh_(c0[bb]);
                }
                // prefetch x(t=p+1) into xbuf[(p+1)&1]
                if (tid < BB && p + 1 < TSEQ)
                    xbuf[rd * 16 + tid] = x[(bbase + tid) * TSEQ + (p + 1)];
            }
        } else {
            if (p >= 1) {
                const float* hr0 = h0buf + rd * 1024 + bg4 * 256;
                const float* hr1 = h1s + bg4 * 256;
                ull acc[4][4];
                #pragma unroll
                for (int g = 0; g < 4; ++g)
                    #pragma unroll
                    for (int bb = 0; bb < 4; ++bb) acc[g][bb] = 0ULL;
                gemm4(acc, WI1A, WI1B, hr0, mB * 4);
                gemm4(acc, WH1A, WH1B, hr1, mB * 4);

                float* hw = h1s + bg4 * 256 + mB;
                #pragma unroll
                for (int bb = 0; bb < 4; ++bb) {
                    float s[4];
                    #pragma unroll
                    for (int g = 0; g < 4; ++g) {
                        float lo, hi;
                        unpack2(acc[g][bb], lo, hi);
                        s[g] = bias1[g] + (lo + hi);
                    }
                    float iv = sigm_(s[0]);
                    float fv = sigm_(s[1]);
                    float gv = tanh_(s[2]);
                    float ov = sigm_(s[3]);
                    c1[bb] = fmaf(fv, c1[bb], iv * gv);
                    hw[bb * 64] = ov * tanh_(c1[bb]);
                }
            }
        }
        __syncthreads();
    }

    // ---- final FC ----
    if (tid < BB * 3) {
        int bb  = tid / 3;
        int cls = tid - bb * 3;
        float s = b_fc[cls];
        #pragma unroll 8
        for (int mm = 0; mm < 64; ++mm)
            s = fmaf(h1s[bb * 64 + mm], w_fc[cls * 64 + mm], s);
        out[(bbase + bb) * 3 + cls] = s;
    }
}

extern "C" void kernel_launch(void* const* d_in, const int* in_sizes, int n_in,
                              void* d_out, int out_size)
{
    const float* x     = (const float*)d_in[0];
    const float* w_ih0 = (const float*)d_in[1];
    const float* w_hh0 = (const float*)d_in[2];
    const float* b_ih0 = (const float*)d_in[3];
    const float* b_hh0 = (const float*)d_in[4];
    const float* w_ih1 = (const float*)d_in[5];
    const float* w_hh1 = (const float*)d_in[6];
    const float* b_ih1 = (const float*)d_in[7];
    const float* b_hh1 = (const float*)d_in[8];
    const float* w_fc  = (const float*)d_in[9];
    const float* b_fc  = (const float*)d_in[10];
    float* out = (float*)d_out;

    cudaFuncSetAttribute(lstm2_fused_kernel,
                         cudaFuncAttributeMaxDynamicSharedMemorySize, SMEM_BYTES);

    lstm2_fused_kernel<<<NBLOCKS, NTHREADS, SMEM_BYTES>>>(
        x, w_ih0, w_hh0, b_ih0, b_hh0,
        w_ih1, w_hh1, b_ih1, b_hh1,
        w_fc, b_fc, out);
}